// round 1
// baseline (speedup 1.0000x reference)
#include <cuda_runtime.h>
#include <math.h>

#define BB 8
#define CC 256
#define SS 16384
#define EPSV 1e-5f

// ---------------- scratch (static device globals; ~9 MB) ----------------
__device__ float g_G [BB*CC*CC];   // X X^T per batch (symmetric)
__device__ float g_P [BB*CC*CC];   // Aq @ G
__device__ float g_L [BB*CC*CC];   // logits -> attn (in place)
__device__ float g_M [BB*CC*CC];   // attn @ Av + I
__device__ float g_Aq[CC*CC];
__device__ float g_Ak[CC*CC];
__device__ float g_AvT[CC*CC];     // Av stored transposed
__device__ float g_bq[CC];
__device__ float g_bk[CC];
__device__ float g_bv[CC];
__device__ float g_s [BB*CC];      // row sums of X
__device__ float g_u [BB*CC];      // Aq @ s
__device__ float g_w [BB*CC];      // Ak @ s
__device__ float g_cv[BB*CC];      // attn @ bv

// ---------------- reductions ----------------
__device__ __forceinline__ float blockReduceSum(float v) {
    __shared__ float sh[8];
    int lane = threadIdx.x & 31, wid = threadIdx.x >> 5;
#pragma unroll
    for (int o = 16; o; o >>= 1) v += __shfl_xor_sync(0xffffffffu, v, o);
    if (lane == 0) sh[wid] = v;
    __syncthreads();
    float r = 0.f;
#pragma unroll
    for (int i = 0; i < 8; i++) r += sh[i];
    __syncthreads();
    return r;
}

__device__ __forceinline__ float blockReduceMax(float v) {
    __shared__ float sh[8];
    int lane = threadIdx.x & 31, wid = threadIdx.x >> 5;
#pragma unroll
    for (int o = 16; o; o >>= 1) v = fmaxf(v, __shfl_xor_sync(0xffffffffu, v, o));
    if (lane == 0) sh[wid] = v;
    __syncthreads();
    float r = -3.402823466e38f;
#pragma unroll
    for (int i = 0; i < 8; i++) r = fmaxf(r, sh[i]);
    __syncthreads();
    return r;
}

// ---------------- prep: fold BN into conv weights ----------------
__global__ void prep_kernel(
    const float* __restrict__ Wk, const float* __restrict__ kg, const float* __restrict__ kb,
    const float* __restrict__ km, const float* __restrict__ kvv,
    const float* __restrict__ Wq, const float* __restrict__ qg, const float* __restrict__ qb,
    const float* __restrict__ qm, const float* __restrict__ qv,
    const float* __restrict__ Wv, const float* __restrict__ vg, const float* __restrict__ vb,
    const float* __restrict__ vm, const float* __restrict__ vv)
{
    int o = blockIdx.x, m = blockIdx.y, i = threadIdx.x;
    const float *W, *ga, *be, *me, *va;
    if (m == 0)      { W = Wq; ga = qg; be = qb; me = qm; va = qv; }
    else if (m == 1) { W = Wk; ga = kg; be = kb; me = km; va = kvv; }
    else             { W = Wv; ga = vg; be = vb; me = vm; va = vv; }
    float inv = ga[o] / sqrtf(va[o] + EPSV);
    float a = inv * W[o*CC + i];
    if (m == 0)      { g_Aq[o*CC + i] = a;  if (i == 0) g_bq[o] = be[o] - me[o]*inv; }
    else if (m == 1) { g_Ak[o*CC + i] = a;  if (i == 0) g_bk[o] = be[o] - me[o]*inv; }
    else             { g_AvT[i*CC + o] = a; if (i == 0) g_bv[o] = be[o] - me[o]*inv; }
}

// ---------------- row sums s[n][c] = sum_s X ----------------
__global__ void rowsum_kernel(const float* __restrict__ x) {
    int c = blockIdx.x, n = blockIdx.y, t = threadIdx.x;
    const float4* xr = (const float4*)(x + ((size_t)n*CC + c)*SS);
    float acc = 0.f;
    for (int i = t; i < SS/4; i += 256) {
        float4 v = xr[i];
        acc += (v.x + v.y) + (v.z + v.w);
    }
    float tot = blockReduceSum(acc);
    if (t == 0) g_s[n*CC + c] = tot;
}

// ---------------- G = X X^T  (64x64 tiles, full-S reduction per CTA) ----------------
__global__ void __launch_bounds__(256) gram_kernel(const float* __restrict__ x) {
    __shared__ float Xis[16*64];
    __shared__ float Xjs[16*64];
    int bj = blockIdx.x, bi = blockIdx.y, n = blockIdx.z;
    int tid = threadIdx.x, tx = tid & 15, ty = tid >> 4;
    int lrow = tid >> 2, lc4 = tid & 3;

    const float* xi = x + ((size_t)n*CC + bi*64 + lrow)*SS + lc4*4;
    const float* xj = x + ((size_t)n*CC + bj*64 + lrow)*SS + lc4*4;

    float acc[4][4] = {};
    float4 a = *(const float4*)xi;
    float4 b = *(const float4*)xj;

    for (int kc = 0; kc < SS; kc += 16) {
        Xis[(lc4*4+0)*64 + lrow] = a.x;
        Xis[(lc4*4+1)*64 + lrow] = a.y;
        Xis[(lc4*4+2)*64 + lrow] = a.z;
        Xis[(lc4*4+3)*64 + lrow] = a.w;
        Xjs[(lc4*4+0)*64 + lrow] = b.x;
        Xjs[(lc4*4+1)*64 + lrow] = b.y;
        Xjs[(lc4*4+2)*64 + lrow] = b.z;
        Xjs[(lc4*4+3)*64 + lrow] = b.w;
        __syncthreads();
        int kn = (kc + 16 < SS) ? kc + 16 : kc;   // prefetch next chunk (redundant on last)
        a = *(const float4*)(xi + kn);
        b = *(const float4*)(xj + kn);
#pragma unroll
        for (int kk = 0; kk < 16; kk++) {
            float4 av = *(const float4*)&Xis[kk*64 + ty*4];
            float4 bv = *(const float4*)&Xjs[kk*64 + tx*4];
            acc[0][0] += av.x*bv.x; acc[0][1] += av.x*bv.y; acc[0][2] += av.x*bv.z; acc[0][3] += av.x*bv.w;
            acc[1][0] += av.y*bv.x; acc[1][1] += av.y*bv.y; acc[1][2] += av.y*bv.z; acc[1][3] += av.y*bv.w;
            acc[2][0] += av.z*bv.x; acc[2][1] += av.z*bv.y; acc[2][2] += av.z*bv.z; acc[2][3] += av.z*bv.w;
            acc[3][0] += av.w*bv.x; acc[3][1] += av.w*bv.y; acc[3][2] += av.w*bv.z; acc[3][3] += av.w*bv.w;
        }
        __syncthreads();
    }

    float* out = g_G + ((size_t)n*CC + bi*64 + ty*4)*CC + bj*64 + tx*4;
#pragma unroll
    for (int u = 0; u < 4; u++) {
        float4 o = make_float4(acc[u][0], acc[u][1], acc[u][2], acc[u][3]);
        *(float4*)(out + (size_t)u*CC) = o;
    }
}

// ---------------- batched 256x256x256 NT GEMM (mode-dispatched) ----------------
// mode 0: P = Aq @ G_n          (G symmetric -> NT ok)
// mode 1: L = P_n @ Ak^T + u[c]*bk[d] + bq[c]*(w[d] + S*bk[d])
// mode 2: M = attn_n @ Av + I   (via AvT, NT form)
__global__ void __launch_bounds__(256) gemm256_nt_kernel(int mode) {
    __shared__ float As[16*64];
    __shared__ float Bs[16*64];
    int bj = blockIdx.x, bi = blockIdx.y, n = blockIdx.z;
    int tid = threadIdx.x, tx = tid & 15, ty = tid >> 4;
    int lrow = tid >> 2, lc4 = tid & 3;

    const float* A; const float* Bm; float* Out;
    if (mode == 0)      { A = g_Aq;                    Bm = g_G + (size_t)n*CC*CC; Out = g_P + (size_t)n*CC*CC; }
    else if (mode == 1) { A = g_P + (size_t)n*CC*CC;   Bm = g_Ak;                  Out = g_L + (size_t)n*CC*CC; }
    else                { A = g_L + (size_t)n*CC*CC;   Bm = g_AvT;                 Out = g_M + (size_t)n*CC*CC; }

    const float* ap = A  + (size_t)(bi*64 + lrow)*CC + lc4*4;
    const float* bp = Bm + (size_t)(bj*64 + lrow)*CC + lc4*4;

    float acc[4][4] = {};
    float4 a = *(const float4*)ap;
    float4 b = *(const float4*)bp;

    for (int kc = 0; kc < CC; kc += 16) {
        As[(lc4*4+0)*64 + lrow] = a.x;
        As[(lc4*4+1)*64 + lrow] = a.y;
        As[(lc4*4+2)*64 + lrow] = a.z;
        As[(lc4*4+3)*64 + lrow] = a.w;
        Bs[(lc4*4+0)*64 + lrow] = b.x;
        Bs[(lc4*4+1)*64 + lrow] = b.y;
        Bs[(lc4*4+2)*64 + lrow] = b.z;
        Bs[(lc4*4+3)*64 + lrow] = b.w;
        __syncthreads();
        int kn = (kc + 16 < CC) ? kc + 16 : kc;
        a = *(const float4*)(ap + kn);
        b = *(const float4*)(bp + kn);
#pragma unroll
        for (int kk = 0; kk < 16; kk++) {
            float4 av = *(const float4*)&As[kk*64 + ty*4];
            float4 bv = *(const float4*)&Bs[kk*64 + tx*4];
            acc[0][0] += av.x*bv.x; acc[0][1] += av.x*bv.y; acc[0][2] += av.x*bv.z; acc[0][3] += av.x*bv.w;
            acc[1][0] += av.y*bv.x; acc[1][1] += av.y*bv.y; acc[1][2] += av.y*bv.z; acc[1][3] += av.y*bv.w;
            acc[2][0] += av.z*bv.x; acc[2][1] += av.z*bv.y; acc[2][2] += av.z*bv.z; acc[2][3] += av.z*bv.w;
            acc[3][0] += av.w*bv.x; acc[3][1] += av.w*bv.y; acc[3][2] += av.w*bv.z; acc[3][3] += av.w*bv.w;
        }
        __syncthreads();
    }

    int row = bi*64 + ty*4;
    int col = bj*64 + tx*4;
    if (mode == 1) {
#pragma unroll
        for (int u = 0; u < 4; u++) {
            float uu = g_u[n*CC + row + u];
            float bb = g_bq[row + u];
#pragma unroll
            for (int v = 0; v < 4; v++) {
                float bk = g_bk[col + v];
                acc[u][v] += uu*bk + bb*(g_w[n*CC + col + v] + (float)SS*bk);
            }
        }
    } else if (mode == 2) {
#pragma unroll
        for (int u = 0; u < 4; u++)
#pragma unroll
            for (int v = 0; v < 4; v++)
                if (row + u == col + v) acc[u][v] += 1.0f;
    }

    float* out = Out + (size_t)row*CC + col;
#pragma unroll
    for (int u = 0; u < 4; u++) {
        float4 o = make_float4(acc[u][0], acc[u][1], acc[u][2], acc[u][3]);
        *(float4*)(out + (size_t)u*CC) = o;
    }
}

// ---------------- small matvecs ----------------
// mode 0: u = Aq @ s_n ; mode 1: w = Ak @ s_n ; mode 2: c = attn_n @ bv
__global__ void matvec_kernel(int mode) {
    int r = blockIdx.x, n = blockIdx.y, t = threadIdx.x;
    const float* Arow; const float* vec; float* out;
    if (mode == 0)      { Arow = g_Aq + (size_t)r*CC;                 vec = g_s + n*CC; out = g_u  + n*CC + r; }
    else if (mode == 1) { Arow = g_Ak + (size_t)r*CC;                 vec = g_s + n*CC; out = g_w  + n*CC + r; }
    else                { Arow = g_L + ((size_t)n*CC + r)*CC;         vec = g_bv;       out = g_cv + n*CC + r; }
    float p = Arow[t] * vec[t];
    float tot = blockReduceSum(p);
    if (t == 0) *out = tot;
}

// ---------------- row softmax over C=256 (in place on g_L) ----------------
__global__ void softmax_kernel() {
    int r = blockIdx.x, n = blockIdx.y, t = threadIdx.x;
    float* row = g_L + ((size_t)n*CC + r)*CC;
    float v = row[t];
    float m = blockReduceMax(v);
    float e = expf(v - m);
    float ss = blockReduceSum(e);
    row[t] = e / ss;
}

// ---------------- out = (M+I) @ X + c  (64 c-rows x 128 s-cols tiles) ----------------
__global__ void __launch_bounds__(256) out_kernel(const float* __restrict__ x, float* __restrict__ out) {
    __shared__ float As[16*64];
    __shared__ float Bs[16*128];
    int bs = blockIdx.x, bc = blockIdx.y, n = blockIdx.z;
    int tid = threadIdx.x, tx = tid & 15, ty = tid >> 4;
    int arow = tid >> 2, ac4 = tid & 3;

    const float* Ap = g_M + ((size_t)n*CC + bc*64 + arow)*CC + ac4*4;
    const float* Xb = x + (size_t)n*CC*SS + (size_t)bs*128;

    float acc[4][8] = {};

    float4 a  = *(const float4*)Ap;
    float4 b0, b1;
    {
        int s0 = tid,        r0 = s0 >> 5, c0 = s0 & 31;
        int s1 = tid + 256,  r1 = s1 >> 5, c1 = s1 & 31;
        b0 = *(const float4*)(Xb + (size_t)r0*SS + c0*4);
        b1 = *(const float4*)(Xb + (size_t)r1*SS + c1*4);
    }

    for (int kc = 0; kc < CC; kc += 16) {
        As[(ac4*4+0)*64 + arow] = a.x;
        As[(ac4*4+1)*64 + arow] = a.y;
        As[(ac4*4+2)*64 + arow] = a.z;
        As[(ac4*4+3)*64 + arow] = a.w;
        {
            int s0 = tid,       r0 = s0 >> 5, c0 = s0 & 31;
            int s1 = tid + 256, r1 = s1 >> 5, c1 = s1 & 31;
            *(float4*)&Bs[r0*128 + c0*4] = b0;
            *(float4*)&Bs[r1*128 + c1*4] = b1;
        }
        __syncthreads();
        int kn = (kc + 16 < CC) ? kc + 16 : kc;
        a = *(const float4*)(Ap + kn);
        {
            int s0 = tid,       r0 = s0 >> 5, c0 = s0 & 31;
            int s1 = tid + 256, r1 = s1 >> 5, c1 = s1 & 31;
            b0 = *(const float4*)(Xb + (size_t)(kn + r0)*SS + c0*4);
            b1 = *(const float4*)(Xb + (size_t)(kn + r1)*SS + c1*4);
        }
#pragma unroll
        for (int kk = 0; kk < 16; kk++) {
            float4 av = *(const float4*)&As[kk*64 + ty*4];
            float4 p0 = *(const float4*)&Bs[kk*128 + tx*8];
            float4 p1 = *(const float4*)&Bs[kk*128 + tx*8 + 4];
            float am[4] = {av.x, av.y, av.z, av.w};
#pragma unroll
            for (int u = 0; u < 4; u++) {
                acc[u][0] += am[u]*p0.x; acc[u][1] += am[u]*p0.y;
                acc[u][2] += am[u]*p0.z; acc[u][3] += am[u]*p0.w;
                acc[u][4] += am[u]*p1.x; acc[u][5] += am[u]*p1.y;
                acc[u][6] += am[u]*p1.z; acc[u][7] += am[u]*p1.w;
            }
        }
        __syncthreads();
    }

#pragma unroll
    for (int u = 0; u < 4; u++) {
        int c = bc*64 + ty*4 + u;
        float cv = g_cv[n*CC + c];
        float* op = out + ((size_t)n*CC + c)*SS + (size_t)bs*128 + tx*8;
        float4 o0 = make_float4(acc[u][0] + cv, acc[u][1] + cv, acc[u][2] + cv, acc[u][3] + cv);
        float4 o1 = make_float4(acc[u][4] + cv, acc[u][5] + cv, acc[u][6] + cv, acc[u][7] + cv);
        *(float4*)op       = o0;
        *(float4*)(op + 4) = o1;
    }
}

// ---------------- launcher ----------------
extern "C" void kernel_launch(void* const* d_in, const int* in_sizes, int n_in,
                              void* d_out, int out_size) {
    const float* x   = (const float*)d_in[0];
    const float* Wk  = (const float*)d_in[1];
    const float* kg  = (const float*)d_in[2];
    const float* kb  = (const float*)d_in[3];
    const float* km  = (const float*)d_in[4];
    const float* kv  = (const float*)d_in[5];
    const float* Wq  = (const float*)d_in[6];
    const float* qg  = (const float*)d_in[7];
    const float* qb  = (const float*)d_in[8];
    const float* qm  = (const float*)d_in[9];
    const float* qv  = (const float*)d_in[10];
    const float* Wv  = (const float*)d_in[11];
    const float* vg  = (const float*)d_in[12];
    const float* vb  = (const float*)d_in[13];
    const float* vm  = (const float*)d_in[14];
    const float* vv  = (const float*)d_in[15];
    float* out = (float*)d_out;

    prep_kernel<<<dim3(CC, 3), CC>>>(Wk, kg, kb, km, kv, Wq, qg, qb, qm, qv, Wv, vg, vb, vm, vv);
    rowsum_kernel<<<dim3(CC, BB), 256>>>(x);
    gram_kernel<<<dim3(4, 4, BB), 256>>>(x);
    gemm256_nt_kernel<<<dim3(4, 4, BB), 256>>>(0);   // P = Aq @ G
    matvec_kernel<<<dim3(CC, BB), 256>>>(0);         // u = Aq @ s
    matvec_kernel<<<dim3(CC, BB), 256>>>(1);         // w = Ak @ s
    gemm256_nt_kernel<<<dim3(4, 4, BB), 256>>>(1);   // L = P @ Ak^T + rank-1 terms
    softmax_kernel<<<dim3(CC, BB), 256>>>();
    gemm256_nt_kernel<<<dim3(4, 4, BB), 256>>>(2);   // M = attn @ Av + I
    matvec_kernel<<<dim3(CC, BB), 256>>>(2);         // c = attn @ bv
    out_kernel<<<dim3(SS/128, CC/64, BB), 256>>>(x, out);
}